// round 4
// baseline (speedup 1.0000x reference)
#include <cuda_runtime.h>

#define N_NODES 100000
#define N_EDGES 600000
#define F_IN 128
#define F_OUT 64
#define TM 128
#define BK 16

// Scratch (no allocation allowed in kernel_launch)
__device__ float s_xp[(size_t)N_NODES * F_OUT];
__device__ float s_deg[N_NODES];
__device__ float s_dis[N_NODES];
__device__ float s_inv_sigma;

// ---------------------------------------------------------------------------
// sigma = ||W (W^T u / ||W^T u||)||  ->  store 1/sigma
// ---------------------------------------------------------------------------
__global__ void k_sigma(const float* __restrict__ W, const float* __restrict__ u) {
    __shared__ float v[F_OUT];
    __shared__ float red[128];
    __shared__ float n1_s;
    int t = threadIdx.x;

    if (t < F_OUT) {
        float s = 0.f;
        for (int i = 0; i < F_IN; i++) s += W[i * F_OUT + t] * u[i];
        v[t] = s;
    }
    __syncthreads();

    red[t] = (t < F_OUT) ? v[t] * v[t] : 0.f;
    __syncthreads();
    for (int s = 64; s > 0; s >>= 1) {
        if (t < s) red[t] += red[t + s];
        __syncthreads();
    }
    if (t == 0) n1_s = sqrtf(red[0]);
    __syncthreads();

    float g = 0.f;
    for (int j = 0; j < F_OUT; j++) g += W[t * F_OUT + j] * v[j];
    red[t] = g * g;
    __syncthreads();
    for (int s = 64; s > 0; s >>= 1) {
        if (t < s) red[t] += red[t + s];
        __syncthreads();
    }
    if (t == 0) {
        float n2 = sqrtf(red[0]);
        s_inv_sigma = n1_s / n2;   // 1/sigma = ||v_raw|| / ||W v_raw||
    }
}

// ---------------------------------------------------------------------------
// Degree: deg[i] = 1 (self loop) + sum_{e: col==i} sigmoid(ew[e])
// ---------------------------------------------------------------------------
__global__ void k_deg_init() {
    int i = blockIdx.x * blockDim.x + threadIdx.x;
    if (i < N_NODES) s_deg[i] = 1.0f;
}

__global__ void k_deg_acc(const int* __restrict__ ei,
                          const float* __restrict__ ew) {
    int e = blockIdx.x * blockDim.x + threadIdx.x;
    if (e < N_EDGES) {
        int col = ei[N_EDGES + e];
        float w = 1.f / (1.f + __expf(-ew[e]));
        atomicAdd(&s_deg[col], w);
    }
}

__global__ void k_dis() {
    int i = blockIdx.x * blockDim.x + threadIdx.x;
    if (i < N_NODES) s_dis[i] = rsqrtf(s_deg[i]);
}

// ---------------------------------------------------------------------------
// xp = x @ (W/sigma); out = xp/deg + bias (self-loop term); stash xp in L2
// Tiled fp32 GEMM: 128 rows/block, 256 threads, 8x4 register tile.
// ---------------------------------------------------------------------------
__global__ __launch_bounds__(256) void k_gemm(const float* __restrict__ x,
                                              const float* __restrict__ W,
                                              const float* __restrict__ bias,
                                              float* __restrict__ out) {
    __shared__ float Ws[F_IN][F_OUT];       // 32 KB (scaled by 1/sigma)
    __shared__ float As[BK][TM + 4];        // transposed A chunk, padded

    int tid = threadIdx.x;
    int tx = tid & 15;      // column group (4 cols each)
    int ty = tid >> 4;      // row group (8 rows each)
    int r0 = blockIdx.x * TM;

    float inv_sigma = s_inv_sigma;
    for (int i = tid; i < F_IN * F_OUT; i += 256)
        (&Ws[0][0])[i] = W[i] * inv_sigma;

    float acc[8][4];
    #pragma unroll
    for (int i = 0; i < 8; i++)
        #pragma unroll
        for (int j = 0; j < 4; j++) acc[i][j] = 0.f;

    for (int kc = 0; kc < F_IN; kc += BK) {
        __syncthreads();
        #pragma unroll
        for (int l = 0; l < 2; l++) {
            int idx = tid + l * 256;        // 0..511 float4 slots
            int row = idx >> 2;             // 0..127
            int kq  = idx & 3;              // 0..3 (float4 within chunk)
            int grow = r0 + row;
            float4 val = make_float4(0.f, 0.f, 0.f, 0.f);
            if (grow < N_NODES)
                val = *(const float4*)&x[(size_t)grow * F_IN + kc + kq * 4];
            As[kq * 4 + 0][row] = val.x;
            As[kq * 4 + 1][row] = val.y;
            As[kq * 4 + 2][row] = val.z;
            As[kq * 4 + 3][row] = val.w;
        }
        __syncthreads();

        #pragma unroll
        for (int k = 0; k < BK; k++) {
            float4 b  = *(const float4*)&Ws[kc + k][tx * 4];
            float4 a0 = *(const float4*)&As[k][ty * 8];
            float4 a1 = *(const float4*)&As[k][ty * 8 + 4];
            float av[8] = {a0.x, a0.y, a0.z, a0.w, a1.x, a1.y, a1.z, a1.w};
            float bv[4] = {b.x, b.y, b.z, b.w};
            #pragma unroll
            for (int i = 0; i < 8; i++)
                #pragma unroll
                for (int j = 0; j < 4; j++)
                    acc[i][j] += av[i] * bv[j];
        }
    }

    float4 b4 = *(const float4*)&bias[tx * 4];
    #pragma unroll
    for (int i = 0; i < 8; i++) {
        int row = r0 + ty * 8 + i;
        if (row < N_NODES) {
            float d = s_dis[row];
            float inv_deg = d * d;
            float4 xpv = make_float4(acc[i][0], acc[i][1], acc[i][2], acc[i][3]);
            *(float4*)&s_xp[(size_t)row * F_OUT + tx * 4] = xpv;
            float4 o = make_float4(xpv.x * inv_deg + b4.x,
                                   xpv.y * inv_deg + b4.y,
                                   xpv.z * inv_deg + b4.z,
                                   xpv.w * inv_deg + b4.w);
            *(float4*)&out[(size_t)row * F_OUT + tx * 4] = o;
        }
    }
}

// ---------------------------------------------------------------------------
// Edge aggregation: out[col] += dis[row]*sigmoid(ew)*dis[col] * xp[row]
// One warp per edge; every lane loads ei/ew (broadcast LDG = 1 transaction).
// Each lane handles 2 features: float2 gather + 2 scalar atomicAdd scatter.
// ---------------------------------------------------------------------------
__global__ __launch_bounds__(256) void k_edge(const int* __restrict__ ei,
                                              const float* __restrict__ ew,
                                              float* __restrict__ out) {
    int gtid = blockIdx.x * blockDim.x + threadIdx.x;
    int e = gtid >> 5;
    int lane = threadIdx.x & 31;
    if (e >= N_EDGES) return;

    int row = ei[e];
    int col = ei[N_EDGES + e];
    float w = 1.f / (1.f + __expf(-ew[e]));
    float coeff = s_dis[row] * w * s_dis[col];

    float2 xv = *(const float2*)&s_xp[(size_t)row * F_OUT + lane * 2];
    float* p = &out[(size_t)col * F_OUT + lane * 2];
    atomicAdd(p + 0, xv.x * coeff);
    atomicAdd(p + 1, xv.y * coeff);
}

// ---------------------------------------------------------------------------
extern "C" void kernel_launch(void* const* d_in, const int* in_sizes, int n_in,
                              void* d_out, int out_size) {
    const float* x    = (const float*)d_in[0];
    const int*   ei   = (const int*)d_in[1];    // edge_index is int32 (JAX x64 off)
    const float* W    = (const float*)d_in[2];
    const float* bias = (const float*)d_in[3];
    const float* ew   = (const float*)d_in[4];
    const float* u    = (const float*)d_in[5];
    float* out = (float*)d_out;

    k_sigma<<<1, 128>>>(W, u);
    k_deg_init<<<(N_NODES + 255) / 256, 256>>>();
    k_deg_acc<<<(N_EDGES + 255) / 256, 256>>>(ei, ew);
    k_dis<<<(N_NODES + 255) / 256, 256>>>();
    k_gemm<<<(N_NODES + TM - 1) / TM, 256>>>(x, W, bias, out);
    // one warp per edge: 600000 warps * 32 / 256 = 75000 blocks
    k_edge<<<75000, 256>>>(ei, ew, out);
}

// round 5
// speedup vs baseline: 1.3225x; 1.3225x over previous
#include <cuda_runtime.h>

#define N_NODES 100000
#define N_EDGES 600000
#define F_IN 128
#define F_OUT 64
#define TM 128
#define BK 16

// Scratch (no allocation allowed in kernel_launch)
__device__ float s_xp[(size_t)N_NODES * F_OUT];
__device__ float s_deg[N_NODES];   // zero-initialized; k_dis re-zeroes after use
__device__ float s_dis[N_NODES];
__device__ float s_inv_sigma;

// ---------------------------------------------------------------------------
// packed fp32x2 helpers (sm_100+: fma.rn.f32x2)
// ---------------------------------------------------------------------------
__device__ __forceinline__ unsigned long long pack2(float lo, float hi) {
    unsigned long long r;
    asm("mov.b64 %0, {%1, %2};" : "=l"(r) : "f"(lo), "f"(hi));
    return r;
}
__device__ __forceinline__ void unpack2(unsigned long long v, float& lo, float& hi) {
    asm("mov.b64 {%0, %1}, %2;" : "=f"(lo), "=f"(hi) : "l"(v));
}
__device__ __forceinline__ void ffma2(unsigned long long& d,
                                      unsigned long long a,
                                      unsigned long long b) {
    asm("fma.rn.f32x2 %0, %1, %2, %0;" : "+l"(d) : "l"(a), "l"(b));
}

// ---------------------------------------------------------------------------
// sigma = ||W (W^T u / ||W^T u||)||  ->  store 1/sigma
// ---------------------------------------------------------------------------
__global__ void k_sigma(const float* __restrict__ W, const float* __restrict__ u) {
    __shared__ float v[F_OUT];
    __shared__ float red[128];
    __shared__ float n1_s;
    int t = threadIdx.x;

    if (t < F_OUT) {
        float s = 0.f;
        for (int i = 0; i < F_IN; i++) s += W[i * F_OUT + t] * u[i];
        v[t] = s;
    }
    __syncthreads();

    red[t] = (t < F_OUT) ? v[t] * v[t] : 0.f;
    __syncthreads();
    for (int s = 64; s > 0; s >>= 1) {
        if (t < s) red[t] += red[t + s];
        __syncthreads();
    }
    if (t == 0) n1_s = sqrtf(red[0]);
    __syncthreads();

    float g = 0.f;
    for (int j = 0; j < F_OUT; j++) g += W[t * F_OUT + j] * v[j];
    red[t] = g * g;
    __syncthreads();
    for (int s = 64; s > 0; s >>= 1) {
        if (t < s) red[t] += red[t + s];
        __syncthreads();
    }
    if (t == 0) {
        float n2 = sqrtf(red[0]);
        s_inv_sigma = n1_s / n2;   // 1/sigma = ||v_raw|| / ||W v_raw||
    }
}

// ---------------------------------------------------------------------------
// deg accumulation (deg starts at 0 each replay; self-loop +1 folded in k_dis)
// ---------------------------------------------------------------------------
__global__ void k_deg_acc(const int* __restrict__ ei,
                          const float* __restrict__ ew) {
    int e = blockIdx.x * blockDim.x + threadIdx.x;
    if (e < N_EDGES) {
        int col = ei[N_EDGES + e];
        float w = 1.f / (1.f + __expf(-ew[e]));
        atomicAdd(&s_deg[col], w);
    }
}

// dis = rsqrt(deg + 1), then reset deg to 0 for the next graph replay
__global__ void k_dis() {
    int i = blockIdx.x * blockDim.x + threadIdx.x;
    if (i < N_NODES) {
        float d = s_deg[i] + 1.0f;
        s_dis[i] = rsqrtf(d);
        s_deg[i] = 0.0f;
    }
}

// ---------------------------------------------------------------------------
// xp = x @ (W/sigma); out = xp/deg + bias (self-loop term); stash xp in L2.
// Tiled fp32 GEMM: 128 rows/block, 256 threads, 8x4 register tile,
// mainloop in packed fma.rn.f32x2 (2 FMA per instruction).
// ---------------------------------------------------------------------------
__global__ __launch_bounds__(256) void k_gemm(const float* __restrict__ x,
                                              const float* __restrict__ W,
                                              const float* __restrict__ bias,
                                              float* __restrict__ out) {
    __shared__ float Ws[F_IN][F_OUT];       // 32 KB (scaled by 1/sigma)
    __shared__ float As[BK][TM + 4];        // transposed A chunk, padded

    int tid = threadIdx.x;
    int tx = tid & 15;      // column group (4 cols each)
    int ty = tid >> 4;      // row group (8 rows each)
    int r0 = blockIdx.x * TM;

    float inv_sigma = s_inv_sigma;
    for (int i = tid; i < F_IN * F_OUT; i += 256)
        (&Ws[0][0])[i] = W[i] * inv_sigma;

    unsigned long long accp[8][2];
    #pragma unroll
    for (int i = 0; i < 8; i++) {
        accp[i][0] = 0ull;
        accp[i][1] = 0ull;
    }

    for (int kc = 0; kc < F_IN; kc += BK) {
        __syncthreads();
        #pragma unroll
        for (int l = 0; l < 2; l++) {
            int idx = tid + l * 256;        // 0..511 float4 slots
            int row = idx >> 2;             // 0..127
            int kq  = idx & 3;              // 0..3 (float4 within chunk)
            int grow = r0 + row;
            float4 val = make_float4(0.f, 0.f, 0.f, 0.f);
            if (grow < N_NODES)
                val = *(const float4*)&x[(size_t)grow * F_IN + kc + kq * 4];
            As[kq * 4 + 0][row] = val.x;
            As[kq * 4 + 1][row] = val.y;
            As[kq * 4 + 2][row] = val.z;
            As[kq * 4 + 3][row] = val.w;
        }
        __syncthreads();

        #pragma unroll
        for (int k = 0; k < BK; k++) {
            // b: 4 cols as two packed f32x2 (16B-aligned smem)
            unsigned long long b01 = *(const unsigned long long*)&Ws[kc + k][tx * 4];
            unsigned long long b23 = *(const unsigned long long*)&Ws[kc + k][tx * 4 + 2];
            float4 a0 = *(const float4*)&As[k][ty * 8];
            float4 a1 = *(const float4*)&As[k][ty * 8 + 4];
            float av[8] = {a0.x, a0.y, a0.z, a0.w, a1.x, a1.y, a1.z, a1.w};
            #pragma unroll
            for (int i = 0; i < 8; i++) {
                unsigned long long ad = pack2(av[i], av[i]);
                ffma2(accp[i][0], ad, b01);
                ffma2(accp[i][1], ad, b23);
            }
        }
    }

    float4 b4 = *(const float4*)&bias[tx * 4];
    #pragma unroll
    for (int i = 0; i < 8; i++) {
        int row = r0 + ty * 8 + i;
        if (row < N_NODES) {
            float d = s_dis[row];
            float inv_deg = d * d;
            float4 xpv;
            unpack2(accp[i][0], xpv.x, xpv.y);
            unpack2(accp[i][1], xpv.z, xpv.w);
            *(float4*)&s_xp[(size_t)row * F_OUT + tx * 4] = xpv;
            float4 o = make_float4(xpv.x * inv_deg + b4.x,
                                   xpv.y * inv_deg + b4.y,
                                   xpv.z * inv_deg + b4.z,
                                   xpv.w * inv_deg + b4.w);
            *(float4*)&out[(size_t)row * F_OUT + tx * 4] = o;
        }
    }
}

// ---------------------------------------------------------------------------
// Edge aggregation: out[col] += dis[row]*sigmoid(ew)*dis[col] * xp[row]
// 2 edges per warp: 16 lanes/edge, each lane one float4 gather + one
// native float4 atomicAdd (sm_90+ vector RED).
// ---------------------------------------------------------------------------
__global__ __launch_bounds__(256) void k_edge(const int* __restrict__ ei,
                                              const float* __restrict__ ew,
                                              float* __restrict__ out) {
    int gtid = blockIdx.x * blockDim.x + threadIdx.x;
    int lane = threadIdx.x & 31;
    int half = lane >> 4;       // which edge within the warp
    int sub  = lane & 15;       // float4 slot within the edge
    int e = (gtid >> 5) * 2 + half;   // 600000 even: always in range

    int row = ei[e];                         // 16-lane broadcast load
    int col = ei[N_EDGES + e];
    float w = 1.f / (1.f + __expf(-ew[e]));
    float coeff = s_dis[row] * w * s_dis[col];

    float4 xv = *(const float4*)&s_xp[(size_t)row * F_OUT + sub * 4];
    float4 m = make_float4(xv.x * coeff, xv.y * coeff, xv.z * coeff, xv.w * coeff);
    atomicAdd((float4*)&out[(size_t)col * F_OUT + sub * 4], m);
}

// ---------------------------------------------------------------------------
extern "C" void kernel_launch(void* const* d_in, const int* in_sizes, int n_in,
                              void* d_out, int out_size) {
    const float* x    = (const float*)d_in[0];
    const int*   ei   = (const int*)d_in[1];    // edge_index is int32 (JAX x64 off)
    const float* W    = (const float*)d_in[2];
    const float* bias = (const float*)d_in[3];
    const float* ew   = (const float*)d_in[4];
    const float* u    = (const float*)d_in[5];
    float* out = (float*)d_out;

    k_sigma<<<1, 128>>>(W, u);
    k_deg_acc<<<(N_EDGES + 255) / 256, 256>>>(ei, ew);
    k_dis<<<(N_NODES + 255) / 256, 256>>>();
    k_gemm<<<(N_NODES + TM - 1) / TM, 256>>>(x, W, bias, out);
    // 2 edges per warp: 600000/2 = 300000 warps / 8 per block = 37500 blocks
    k_edge<<<37500, 256>>>(ei, ew, out);
}